// round 1
// baseline (speedup 1.0000x reference)
#include <cuda_runtime.h>

#define HW 512
#define PLANES 32          // B*C = 16*2
#define STRIPS 16
#define SROWS (HW / STRIPS)  // 32
#define TPB 128              // 4 columns per thread
#define VW (HW + 8)          // 520, 4-halo each side (zero padded)

#define GN (16 * 2 * 256 * 256)   // dvf elements
#define GBLOCKS 256
#define GTPB 256

// scratch (no cudaMalloc allowed)
__device__ float g_ncc_part[PLANES * STRIPS];   // 512
__device__ float g_dx_part[GBLOCKS];
__device__ float g_dy_part[GBLOCKS];

__device__ __forceinline__ float4 ld4(const float* __restrict__ p, int r, int x0) {
    if ((unsigned)r < (unsigned)HW)
        return *reinterpret_cast<const float4*>(p + (size_t)r * HW + x0);
    return make_float4(0.f, 0.f, 0.f, 0.f);
}

// horizontal 9-sum for 4 consecutive output columns via register sliding
__device__ __forceinline__ void hsum9(const float* __restrict__ Vq, int x0, float* __restrict__ h) {
    __align__(16) float w[12];
    *reinterpret_cast<float4*>(&w[0]) = *reinterpret_cast<const float4*>(&Vq[x0]);
    *reinterpret_cast<float4*>(&w[4]) = *reinterpret_cast<const float4*>(&Vq[x0 + 4]);
    *reinterpret_cast<float4*>(&w[8]) = *reinterpret_cast<const float4*>(&Vq[x0 + 8]);
    float h0 = w[0] + w[1] + w[2] + w[3] + w[4] + w[5] + w[6] + w[7] + w[8];
    h[0] = h0;
    h[1] = h0   - w[0] + w[9];
    h[2] = h[1] - w[1] + w[10];
    h[3] = h[2] - w[2] + w[11];
}

__global__ __launch_bounds__(TPB) void ncc_kernel(const float* __restrict__ gI,
                                                  const float* __restrict__ gJ) {
    const int strip = blockIdx.x;
    const int plane = blockIdx.y;
    const float* I = gI + (size_t)plane * HW * HW;
    const float* J = gJ + (size_t)plane * HW * HW;

    __shared__ __align__(16) float VI[VW], VJ[VW], VI2[VW], VJ2[VW], VIJ[VW];
    __shared__ float red[TPB];

    const int t = threadIdx.x;
    const int x0 = t * 4;

    for (int i = t; i < VW; i += TPB) {
        VI[i] = 0.f; VJ[i] = 0.f; VI2[i] = 0.f; VJ2[i] = 0.f; VIJ[i] = 0.f;
    }
    __syncthreads();

    // vertical running sums for this thread's 4 columns, held in registers
    __align__(16) float sI[4]  = {0.f, 0.f, 0.f, 0.f};
    __align__(16) float sJ[4]  = {0.f, 0.f, 0.f, 0.f};
    __align__(16) float sI2[4] = {0.f, 0.f, 0.f, 0.f};
    __align__(16) float sJ2[4] = {0.f, 0.f, 0.f, 0.f};
    __align__(16) float sIJ[4] = {0.f, 0.f, 0.f, 0.f};

    const int y0 = strip * SROWS;

    auto addrow = [&](int r, float sgn) {
        float4 a = ld4(I, r, x0);
        float4 b = ld4(J, r, x0);
        const float* ap = reinterpret_cast<const float*>(&a);
        const float* bp = reinterpret_cast<const float*>(&b);
#pragma unroll
        for (int k = 0; k < 4; ++k) {
            float iv = ap[k], jv = bp[k];
            float siv = sgn * iv, sjv = sgn * jv;
            sI[k]  += siv;
            sJ[k]  += sjv;
            sI2[k] = fmaf(siv, iv, sI2[k]);
            sJ2[k] = fmaf(sjv, jv, sJ2[k]);
            sIJ[k] = fmaf(siv, jv, sIJ[k]);
        }
    };

    // warm-up: rows [y0-4, y0+3]
#pragma unroll
    for (int r = y0 - 4; r <= y0 + 3; ++r) addrow(r, 1.f);

    const float inv81 = 1.f / 81.f;
    float acc = 0.f;

    for (int y = y0; y < y0 + SROWS; ++y) {
        // slide: window becomes [y-4, y+4]
        addrow(y + 4, 1.f);
        if (y > y0) addrow(y - 5, -1.f);

        // publish to shared for horizontal pass
        *reinterpret_cast<float4*>(&VI[4 + x0])  = *reinterpret_cast<float4*>(sI);
        *reinterpret_cast<float4*>(&VJ[4 + x0])  = *reinterpret_cast<float4*>(sJ);
        *reinterpret_cast<float4*>(&VI2[4 + x0]) = *reinterpret_cast<float4*>(sI2);
        *reinterpret_cast<float4*>(&VJ2[4 + x0]) = *reinterpret_cast<float4*>(sJ2);
        *reinterpret_cast<float4*>(&VIJ[4 + x0]) = *reinterpret_cast<float4*>(sIJ);
        __syncthreads();

        float hI[4], hJ[4], hI2[4], hJ2[4], hIJ[4];
        hsum9(VI,  x0, hI);
        hsum9(VJ,  x0, hJ);
        hsum9(VI2, x0, hI2);
        hsum9(VJ2, x0, hJ2);
        hsum9(VIJ, x0, hIJ);

#pragma unroll
        for (int k = 0; k < 4; ++k) {
            float Is = hI[k], Js = hJ[k];
            float uI = Is * inv81, uJ = Js * inv81;
            float cross = hIJ[k] - uJ * Is - uI * Js + uI * uJ * 81.f;
            float Ivar  = hI2[k] - 2.f * uI * Is + uI * uI * 81.f;
            float Jvar  = hJ2[k] - 2.f * uJ * Js + uJ * uJ * 81.f;
            acc += __fdividef(cross * cross, fmaf(Ivar, Jvar, 1e-5f));
        }
        __syncthreads();
    }

    // block reduction (fixed topology -> deterministic)
    red[t] = acc;
    __syncthreads();
#pragma unroll
    for (int s = TPB / 2; s > 0; s >>= 1) {
        if (t < s) red[t] += red[t + s];
        __syncthreads();
    }
    if (t == 0) g_ncc_part[plane * STRIPS + strip] = red[0];
}

__global__ __launch_bounds__(GTPB) void grad_kernel(const float* __restrict__ v) {
    __shared__ float rx[GTPB], ry[GTPB];
    const int tid = blockIdx.x * GTPB + threadIdx.x;
    float ax = 0.f, ay = 0.f;
    for (int i = tid; i < GN; i += GBLOCKS * GTPB) {
        float c = v[i];
        int x = i & 255;
        int y = (i >> 8) & 255;
        if (x < 255) { float d = v[i + 1] - c;   ax = fmaf(d, d, ax); }
        if (y < 255) { float d = v[i + 256] - c; ay = fmaf(d, d, ay); }
    }
    rx[threadIdx.x] = ax;
    ry[threadIdx.x] = ay;
    __syncthreads();
#pragma unroll
    for (int s = GTPB / 2; s > 0; s >>= 1) {
        if (threadIdx.x < s) {
            rx[threadIdx.x] += rx[threadIdx.x + s];
            ry[threadIdx.x] += ry[threadIdx.x + s];
        }
        __syncthreads();
    }
    if (threadIdx.x == 0) {
        g_dx_part[blockIdx.x] = rx[0];
        g_dy_part[blockIdx.x] = ry[0];
    }
}

__global__ __launch_bounds__(512) void finalize_kernel(float* __restrict__ out, int out_size) {
    __shared__ double sh[512];
    const int t = threadIdx.x;

    // reduce NCC partials (512 entries)
    sh[t] = (double)g_ncc_part[t];
    __syncthreads();
#pragma unroll
    for (int s = 256; s > 0; s >>= 1) {
        if (t < s) sh[t] += sh[t + s];
        __syncthreads();
    }
    double Sncc = sh[0];
    __syncthreads();

    // reduce grad partials (dx+dy share the same denominator count)
    sh[t] = (t < GBLOCKS) ? (double)g_dx_part[t] + (double)g_dy_part[t] : 0.0;
    __syncthreads();
#pragma unroll
    for (int s = 256; s > 0; s >>= 1) {
        if (t < s) sh[t] += sh[t + s];
        __syncthreads();
    }
    double Sg = sh[0];

    if (t == 0) {
        // ncc = -sum(cc) / (B*H*W); (C-1) == 1
        double ncc  = -Sncc / 4194304.0;                 // 16*512*512
        double grad = 0.01 * (Sg / 2088960.0);           // 16*2*256*255
        double total = ncc + grad;
        if (out_size > 0) out[0] = (float)total;
        if (out_size > 1) out[1] = (float)ncc;
        if (out_size > 2) out[2] = (float)grad;
    }
}

extern "C" void kernel_launch(void* const* d_in, const int* in_sizes, int n_in,
                              void* d_out, int out_size) {
    const float* y_true = (const float*)d_in[0];
    const float* y_pred = (const float*)d_in[1];
    const float* dvf    = (const float*)d_in[2];

    dim3 grid(STRIPS, PLANES);
    ncc_kernel<<<grid, TPB>>>(y_true, y_pred);
    grad_kernel<<<GBLOCKS, GTPB>>>(dvf);
    finalize_kernel<<<1, 512>>>((float*)d_out, out_size);
}

// round 2
// speedup vs baseline: 1.3147x; 1.3147x over previous
#include <cuda_runtime.h>

#define HW 512
#define PLANES 32            // B*C = 16*2
#define STRIPS 32
#define SROWS (HW / STRIPS)  // 16
#define TPB 128              // 4 columns per thread
#define VW (HW + 8)          // 520, 4-halo each side (zero padded)

#define GN (16 * 2 * 256 * 256)   // dvf elements
#define GBLOCKS 256
#define GTPB 256

// scratch (no cudaMalloc allowed)
__device__ float g_ncc_part[PLANES * STRIPS];   // 1024
__device__ float g_dx_part[GBLOCKS];
__device__ float g_dy_part[GBLOCKS];

__device__ __forceinline__ float4 ld4(const float* __restrict__ p, int r, int x0) {
    if ((unsigned)r < (unsigned)HW)
        return *reinterpret_cast<const float4*>(p + (size_t)r * HW + x0);
    return make_float4(0.f, 0.f, 0.f, 0.f);
}

// horizontal 9-sum: own 4 vertical sums stay in registers, only neighbors come
// from shared. L = V[x0..x0+3] (left neighbor), R = V[x0+8..x0+11] (right).
__device__ __forceinline__ void hsum9(const float4 L, const float4 R,
                                      const float* __restrict__ O,
                                      float* __restrict__ h) {
    float h0 = ((L.x + L.y) + (L.z + L.w)) + ((O[0] + O[1]) + (O[2] + O[3])) + R.x;
    h[0] = h0;
    h[1] = h0   - L.x + R.y;
    h[2] = h[1] - L.y + R.z;
    h[3] = h[2] - L.z + R.w;
}

__global__ __launch_bounds__(TPB, 8) void ncc_kernel(const float* __restrict__ gI,
                                                     const float* __restrict__ gJ) {
    const int strip = blockIdx.x;
    const int plane = blockIdx.y;
    const float* I = gI + (size_t)plane * HW * HW;
    const float* J = gJ + (size_t)plane * HW * HW;

    // double-buffered row-sum arrays: [buf][quantity][col]
    __shared__ __align__(16) float V[2][5][VW];
    __shared__ float red[TPB];

    const int t = threadIdx.x;
    const int x0 = t * 4;

    for (int i = t; i < VW; i += TPB) {
#pragma unroll
        for (int b = 0; b < 2; ++b)
#pragma unroll
            for (int q = 0; q < 5; ++q)
                V[b][q][i] = 0.f;
    }
    __syncthreads();

    // vertical running sums for this thread's 4 columns, held in registers
    __align__(16) float sI[4]  = {0.f, 0.f, 0.f, 0.f};
    __align__(16) float sJ[4]  = {0.f, 0.f, 0.f, 0.f};
    __align__(16) float sI2[4] = {0.f, 0.f, 0.f, 0.f};
    __align__(16) float sJ2[4] = {0.f, 0.f, 0.f, 0.f};
    __align__(16) float sIJ[4] = {0.f, 0.f, 0.f, 0.f};

    const int y0 = strip * SROWS;

    auto addrow = [&](int r) {
        float4 a = ld4(I, r, x0);
        float4 b = ld4(J, r, x0);
        const float* ap = reinterpret_cast<const float*>(&a);
        const float* bp = reinterpret_cast<const float*>(&b);
#pragma unroll
        for (int k = 0; k < 4; ++k) {
            float iv = ap[k], jv = bp[k];
            sI[k]  += iv;
            sJ[k]  += jv;
            sI2[k] = fmaf(iv, iv, sI2[k]);
            sJ2[k] = fmaf(jv, jv, sJ2[k]);
            sIJ[k] = fmaf(iv, jv, sIJ[k]);
        }
    };
    auto subrow = [&](int r) {
        float4 a = ld4(I, r, x0);
        float4 b = ld4(J, r, x0);
        const float* ap = reinterpret_cast<const float*>(&a);
        const float* bp = reinterpret_cast<const float*>(&b);
#pragma unroll
        for (int k = 0; k < 4; ++k) {
            float iv = ap[k], jv = bp[k];
            sI[k]  -= iv;
            sJ[k]  -= jv;
            sI2[k] = fmaf(-iv, iv, sI2[k]);
            sJ2[k] = fmaf(-jv, jv, sJ2[k]);
            sIJ[k] = fmaf(-iv, jv, sIJ[k]);
        }
    };

    // warm-up: rows [y0-4, y0+3]
#pragma unroll
    for (int r = y0 - 4; r <= y0 + 3; ++r) addrow(r);

    const float inv81 = 1.f / 81.f;
    float acc = 0.f;

    for (int y = y0; y < y0 + SROWS; ++y) {
        // slide: window becomes [y-4, y+4]
        addrow(y + 4);
        if (y > y0) subrow(y - 5);

        const int buf = y & 1;
        float (* __restrict__ Vb)[VW] = V[buf];

        // publish own vertical sums (halo cols [0..3],[516..519] stay zero)
        *reinterpret_cast<float4*>(&Vb[0][4 + x0]) = *reinterpret_cast<float4*>(sI);
        *reinterpret_cast<float4*>(&Vb[1][4 + x0]) = *reinterpret_cast<float4*>(sJ);
        *reinterpret_cast<float4*>(&Vb[2][4 + x0]) = *reinterpret_cast<float4*>(sI2);
        *reinterpret_cast<float4*>(&Vb[3][4 + x0]) = *reinterpret_cast<float4*>(sJ2);
        *reinterpret_cast<float4*>(&Vb[4][4 + x0]) = *reinterpret_cast<float4*>(sIJ);
        __syncthreads();   // single barrier per row (double buffering covers reuse)

        float hI[4], hJ[4], hI2[4], hJ2[4], hIJ[4];
        hsum9(*reinterpret_cast<const float4*>(&Vb[0][x0]),
              *reinterpret_cast<const float4*>(&Vb[0][x0 + 8]), sI,  hI);
        hsum9(*reinterpret_cast<const float4*>(&Vb[1][x0]),
              *reinterpret_cast<const float4*>(&Vb[1][x0 + 8]), sJ,  hJ);
        hsum9(*reinterpret_cast<const float4*>(&Vb[2][x0]),
              *reinterpret_cast<const float4*>(&Vb[2][x0 + 8]), sI2, hI2);
        hsum9(*reinterpret_cast<const float4*>(&Vb[3][x0]),
              *reinterpret_cast<const float4*>(&Vb[3][x0 + 8]), sJ2, hJ2);
        hsum9(*reinterpret_cast<const float4*>(&Vb[4][x0]),
              *reinterpret_cast<const float4*>(&Vb[4][x0 + 8]), sIJ, hIJ);

#pragma unroll
        for (int k = 0; k < 4; ++k) {
            float Is = hI[k], Js = hJ[k];
            float uI = Is * inv81, uJ = Js * inv81;
            float cross = hIJ[k] - uJ * Is - uI * Js + uI * uJ * 81.f;
            float Ivar  = hI2[k] - 2.f * uI * Is + uI * uI * 81.f;
            float Jvar  = hJ2[k] - 2.f * uJ * Js + uJ * uJ * 81.f;
            acc += __fdividef(cross * cross, fmaf(Ivar, Jvar, 1e-5f));
        }
    }

    // block reduction (fixed topology -> deterministic)
    __syncthreads();
    red[t] = acc;
    __syncthreads();
#pragma unroll
    for (int s = TPB / 2; s > 0; s >>= 1) {
        if (t < s) red[t] += red[t + s];
        __syncthreads();
    }
    if (t == 0) g_ncc_part[plane * STRIPS + strip] = red[0];
}

__global__ __launch_bounds__(GTPB) void grad_kernel(const float* __restrict__ v) {
    __shared__ float rx[GTPB], ry[GTPB];
    const int tid = blockIdx.x * GTPB + threadIdx.x;
    float ax = 0.f, ay = 0.f;
    for (int i = tid; i < GN; i += GBLOCKS * GTPB) {
        float c = v[i];
        int x = i & 255;
        int y = (i >> 8) & 255;
        if (x < 255) { float d = v[i + 1] - c;   ax = fmaf(d, d, ax); }
        if (y < 255) { float d = v[i + 256] - c; ay = fmaf(d, d, ay); }
    }
    rx[threadIdx.x] = ax;
    ry[threadIdx.x] = ay;
    __syncthreads();
#pragma unroll
    for (int s = GTPB / 2; s > 0; s >>= 1) {
        if (threadIdx.x < s) {
            rx[threadIdx.x] += rx[threadIdx.x + s];
            ry[threadIdx.x] += ry[threadIdx.x + s];
        }
        __syncthreads();
    }
    if (threadIdx.x == 0) {
        g_dx_part[blockIdx.x] = rx[0];
        g_dy_part[blockIdx.x] = ry[0];
    }
}

__global__ __launch_bounds__(1024) void finalize_kernel(float* __restrict__ out, int out_size) {
    __shared__ double sh[1024];
    const int t = threadIdx.x;

    // reduce NCC partials (1024 entries)
    sh[t] = (double)g_ncc_part[t];
    __syncthreads();
#pragma unroll
    for (int s = 512; s > 0; s >>= 1) {
        if (t < s) sh[t] += sh[t + s];
        __syncthreads();
    }
    double Sncc = sh[0];
    __syncthreads();

    // reduce grad partials (dx+dy share the same denominator count)
    sh[t] = (t < GBLOCKS) ? (double)g_dx_part[t] + (double)g_dy_part[t] : 0.0;
    __syncthreads();
#pragma unroll
    for (int s = 512; s > 0; s >>= 1) {
        if (t < s) sh[t] += sh[t + s];
        __syncthreads();
    }
    double Sg = sh[0];

    if (t == 0) {
        // ncc = -sum(cc) / (B*H*W); (C-1) == 1
        double ncc  = -Sncc / 4194304.0;                 // 16*512*512
        double grad = 0.01 * (Sg / 2088960.0);           // 16*2*256*255
        double total = ncc + grad;
        if (out_size > 0) out[0] = (float)total;
        if (out_size > 1) out[1] = (float)ncc;
        if (out_size > 2) out[2] = (float)grad;
    }
}

extern "C" void kernel_launch(void* const* d_in, const int* in_sizes, int n_in,
                              void* d_out, int out_size) {
    const float* y_true = (const float*)d_in[0];
    const float* y_pred = (const float*)d_in[1];
    const float* dvf    = (const float*)d_in[2];

    dim3 grid(STRIPS, PLANES);
    ncc_kernel<<<grid, TPB>>>(y_true, y_pred);
    grad_kernel<<<GBLOCKS, GTPB>>>(dvf);
    finalize_kernel<<<1, 1024>>>((float*)d_out, out_size);
}